// round 1
// baseline (speedup 1.0000x reference)
#include <cuda_runtime.h>

// SConv2dAvg: stochastic strided conv.
// out[b,o,y,x] = sum_{c,r,s} input[b,c, 2y+selh[y,x]+r, 2x+selw[y,x]+s] * weight[o,c,r,s] + bias[o]
// B=16, Cin=64, H=W=128, Cout=64, k=3x3, oh=ow=63, STRIDE=2.

#define OHW    63
#define NPIX   (63 * 63)        // 3969
#define CIN    64
#define COUT   64
#define NB     16
#define KTOT   576              // Cin*3*3
#define KC     96               // k-chunk staged in smem
#define NCHUNK (KTOT / KC)      // 6
#define THREADS 256
#define SMEM_BYTES ((2 * NB * KTOT + KC * COUT) * 4)   // 98304

// Weight transposed to k-major [576][64] so per-block chunk loads are coalesced.
__device__ float g_wT[KTOT * COUT];

__global__ void transpose_w_kernel(const float* __restrict__ w) {
    int idx = blockIdx.x * 256 + threadIdx.x;
    if (idx < KTOT * COUT) {
        int k = idx >> 6;      // 0..575
        int o = idx & 63;
        g_wT[idx] = w[o * KTOT + k];
    }
}

__global__ __launch_bounds__(THREADS) void sconv_kernel(
    const float* __restrict__ input,
    const float* __restrict__ bias,
    const int*   __restrict__ selh,
    const int*   __restrict__ selw,
    float*       __restrict__ out)
{
    extern __shared__ float smem[];
    float* patch = smem;                    // [2][16][576] = 18432 floats
    float* wsh   = smem + 2 * NB * KTOT;    // [96][64]     =  6144 floats

    const int tid = threadIdx.x;
    const int px0 = blockIdx.x * 2;

    // Per-pixel gather base offsets (all threads read same sel -> broadcast loads)
    int  base_in[2];
    bool valid[2];
#pragma unroll
    for (int p = 0; p < 2; p++) {
        int px   = px0 + p;
        valid[p] = (px < NPIX);
        int pxc  = valid[p] ? px : 0;
        int y    = pxc / OHW;
        int x    = pxc - y * OHW;
        int ih0  = 2 * y + selh[pxc];
        int iw0  = 2 * x + selw[pxc];
        base_in[p] = ih0 * 128 + iw0;       // offset within one (b,c) 128x128 plane
    }

    // Stage both pixels' patches: 2*16*576 = 18432 elements, 72 per thread.
    for (int idx = tid; idx < 2 * NB * KTOT; idx += THREADS) {
        int p   = (idx >= NB * KTOT) ? 1 : 0;
        int rem = idx - p * (NB * KTOT);
        int b   = rem / KTOT;
        int k   = rem - b * KTOT;
        int c   = k / 9;
        int rs  = k - c * 9;
        int r   = rs / 3;
        int s   = rs - r * 3;
        patch[idx] = input[((b * CIN + c) << 14) + base_in[p] + r * 128 + s];
    }

    const int lane = tid & 31;
    const int warp = tid >> 5;              // 0..7 -> batches {2w, 2w+1}
    const int o2   = lane * 2;              // this thread's output channels o2, o2+1

    const float* pp0a = patch + (0 * NB + warp * 2    ) * KTOT;
    const float* pp0b = patch + (0 * NB + warp * 2 + 1) * KTOT;
    const float* pp1a = patch + (1 * NB + warp * 2    ) * KTOT;
    const float* pp1b = patch + (1 * NB + warp * 2 + 1) * KTOT;

    float a000 = 0.f, a001 = 0.f, a010 = 0.f, a011 = 0.f;
    float a100 = 0.f, a101 = 0.f, a110 = 0.f, a111 = 0.f;

    for (int ch = 0; ch < NCHUNK; ch++) {
        __syncthreads();                    // protect wsh from prior chunk readers / patch writes
        // Coalesced chunk copy: 6144 floats = 1536 float4, 6 per thread.
        const float4* src = (const float4*)(g_wT + ch * KC * COUT);
        float4*       dst = (float4*)wsh;
        for (int i = tid; i < KC * COUT / 4; i += THREADS)
            dst[i] = src[i];
        __syncthreads();

        const int kb = ch * KC;
#pragma unroll 8
        for (int kk = 0; kk < KC; kk++) {
            float2 w = *(const float2*)(wsh + kk * COUT + o2);  // conflict-free LDS.64
            int k = kb + kk;
            float p0a = pp0a[k];            // warp-uniform address -> broadcast
            float p0b = pp0b[k];
            float p1a = pp1a[k];
            float p1b = pp1b[k];
            a000 += w.x * p0a;  a001 += w.y * p0a;
            a010 += w.x * p0b;  a011 += w.y * p0b;
            a100 += w.x * p1a;  a101 += w.y * p1a;
            a110 += w.x * p1b;  a111 += w.y * p1b;
        }
    }

    const float2 bb = *(const float2*)(bias + o2);
    const int b0 = warp * 2, b1 = warp * 2 + 1;

    if (valid[0]) {
        int px = px0;
        out[(b0 * COUT + o2    ) * NPIX + px] = a000 + bb.x;
        out[(b0 * COUT + o2 + 1) * NPIX + px] = a001 + bb.y;
        out[(b1 * COUT + o2    ) * NPIX + px] = a010 + bb.x;
        out[(b1 * COUT + o2 + 1) * NPIX + px] = a011 + bb.y;
    }
    if (valid[1]) {
        int px = px0 + 1;
        out[(b0 * COUT + o2    ) * NPIX + px] = a100 + bb.x;
        out[(b0 * COUT + o2 + 1) * NPIX + px] = a101 + bb.y;
        out[(b1 * COUT + o2    ) * NPIX + px] = a110 + bb.x;
        out[(b1 * COUT + o2 + 1) * NPIX + px] = a111 + bb.y;
    }
}

extern "C" void kernel_launch(void* const* d_in, const int* in_sizes, int n_in,
                              void* d_out, int out_size)
{
    const float* input  = (const float*)d_in[0];
    const float* weight = (const float*)d_in[1];
    const float* bias   = (const float*)d_in[2];
    const int*   selh   = (const int*)d_in[3];
    const int*   selw   = (const int*)d_in[4];
    float*       out    = (float*)d_out;

    cudaFuncSetAttribute(sconv_kernel,
                         cudaFuncAttributeMaxDynamicSharedMemorySize, SMEM_BYTES);

    transpose_w_kernel<<<(KTOT * COUT + 255) / 256, 256>>>(weight);
    sconv_kernel<<<(NPIX + 1) / 2, THREADS, SMEM_BYTES>>>(input, bias, selh, selw, out);
}